// round 9
// baseline (speedup 1.0000x reference)
#include <cuda_runtime.h>

// Problem constants (fixed by the dataset)
#define NN 100000
#define EMAX 3200000
#define SCAN_B 1024
#define SCAN_G ((NN + SCAN_B - 1) / SCAN_B)   // 98

// ---------------- scratch (static __device__, no allocation) ----------------
// s-side layer-1 record packed into ONE 32B sector: {als[4], x0, x1, pad}
struct __align__(32) Src1 { float4 als; float2 x; float2 pad; };
__device__ Src1  g_src1[NN];
__device__ float4 g_ald1[NN];     // per-node att-dst logits (own-node read, coalesced)
__device__ float4 g_nd2[NN];      // layer2 node record: (als2, ald2, h2x, h2y)
// CSR build
__device__ int g_cnt[NN];
__device__ int g_scan[NN];
__device__ int g_bsum[SCAN_G];
__device__ int g_boff[SCAN_G];
__device__ int g_off[NN];
__device__ int g_pos[NN];
__device__ int g_ss[EMAX];        // src node ids bucketed by dst

// ---------------- helpers ----------------
__device__ __forceinline__ float lrelu(float v) { return v > 0.f ? v : 0.2f * v; }

// ============================================================================
// K1: layer-1 node prep: logits from x@W1 (rank-1, h1 never materialized),
//     also zeroes the CSR histogram.
// ============================================================================
__global__ void k1_node(const float* __restrict__ x, const float* __restrict__ W1,
                        const float* __restrict__ asrc, const float* __restrict__ adst) {
    int n = blockIdx.x * blockDim.x + threadIdx.x;
    if (n >= NN) return;
    float x0 = x[2 * n], x1 = x[2 * n + 1];
    float als[4], ald[4];
#pragma unroll
    for (int hd = 0; hd < 4; hd++) {
        float s = 0.f, d = 0.f;
#pragma unroll
        for (int c = 0; c < 8; c++) {
            int k = hd * 8 + c;
            float h = x0 * __ldg(&W1[k]) + x1 * __ldg(&W1[32 + k]);
            s += h * __ldg(&asrc[k]);
            d += h * __ldg(&adst[k]);
        }
        als[hd] = s; ald[hd] = d;
    }
    g_src1[n].als = make_float4(als[0], als[1], als[2], als[3]);
    g_src1[n].x   = make_float2(x0, x1);
    g_src1[n].pad = make_float2(0.f, 0.f);
    g_ald1[n] = make_float4(ald[0], ald[1], ald[2], ald[3]);
    g_cnt[n] = 0;
}

// ============================================================================
// CSR build: histogram -> scan -> scatter
// ============================================================================
__global__ void khist(const int* __restrict__ ei, int E) {
    int e = blockIdx.x * blockDim.x + threadIdx.x;
    if (e >= E) return;
    int s = ei[e];
    int d = ei[E + e];
    if ((unsigned)s >= NN || (unsigned)d >= NN) return;
    atomicAdd(&g_cnt[d], 1);
}

__global__ void kscanA(void) {
    __shared__ int sh[SCAN_B];
    int t = threadIdx.x;
    int g = blockIdx.x * SCAN_B + t;
    int v = (g < NN) ? g_cnt[g] : 0;
    sh[t] = v;
    __syncthreads();
    for (int ofs = 1; ofs < SCAN_B; ofs <<= 1) {
        int add = (t >= ofs) ? sh[t - ofs] : 0;
        __syncthreads();
        sh[t] += add;
        __syncthreads();
    }
    if (g < NN) g_scan[g] = sh[t];
    if (t == SCAN_B - 1) g_bsum[blockIdx.x] = sh[t];
}

__global__ void kscanB(void) {
    __shared__ int sh[128];
    int t = threadIdx.x;
    int v = (t < SCAN_G) ? g_bsum[t] : 0;
    sh[t] = v;
    __syncthreads();
    for (int ofs = 1; ofs < 128; ofs <<= 1) {
        int add = (t >= ofs) ? sh[t - ofs] : 0;
        __syncthreads();
        sh[t] += add;
        __syncthreads();
    }
    if (t < SCAN_G) g_boff[t] = sh[t] - v;   // exclusive
}

__global__ void kscanC(void) {
    int n = blockIdx.x * blockDim.x + threadIdx.x;
    if (n >= NN) return;
    int excl = g_boff[n / SCAN_B] + g_scan[n] - g_cnt[n];
    g_off[n] = excl;
    g_pos[n] = excl;
}

__global__ void kscatter(const int* __restrict__ ei, int E) {
    int e = blockIdx.x * blockDim.x + threadIdx.x;
    if (e >= E) return;
    int s = ei[e];
    int d = ei[E + e];
    if ((unsigned)s >= NN || (unsigned)d >= NN) return;
    int p = atomicAdd(&g_pos[d], 1);
    g_ss[p] = s;
}

// ============================================================================
// KL1: per-node layer-1: loop incoming edges, register accumulation (no atomics),
//      fused epilogue (normalize + bias + ELU + layer-2 transform + logits).
// ============================================================================
__global__ void kL1(const float* __restrict__ W1, const float* __restrict__ b1,
                    const float* __restrict__ W2,
                    const float* __restrict__ as2, const float* __restrict__ ad2) {
    int n = blockIdx.x * blockDim.x + threadIdx.x;
    if (n >= NN) return;
    float4 ald = g_ald1[n];
    float4 oas = g_src1[n].als;
    float2 ox  = g_src1[n].x;
    // self-loop seed
    float w0 = __expf(lrelu(oas.x + ald.x));
    float w1 = __expf(lrelu(oas.y + ald.y));
    float w2 = __expf(lrelu(oas.z + ald.z));
    float w3 = __expf(lrelu(oas.w + ald.w));
    float dn0 = w0, dn1 = w1, dn2 = w2, dn3 = w3;
    float A0 = w0 * ox.x, A1 = w1 * ox.x, A2 = w2 * ox.x, A3 = w3 * ox.x;
    float B0 = w0 * ox.y, B1 = w1 * ox.y, B2 = w2 * ox.y, B3 = w3 * ox.y;
    int beg = g_off[n];
    int end = beg + g_cnt[n];
#pragma unroll 4
    for (int j = beg; j < end; j++) {
        int s = __ldg(&g_ss[j]);
        float4 as = __ldg(&g_src1[s].als);
        float2 xs = __ldg(&g_src1[s].x);   // same 32B sector
        float e0 = __expf(lrelu(as.x + ald.x));
        float e1 = __expf(lrelu(as.y + ald.y));
        float e2 = __expf(lrelu(as.z + ald.z));
        float e3 = __expf(lrelu(as.w + ald.w));
        dn0 += e0; dn1 += e1; dn2 += e2; dn3 += e3;
        A0 += e0 * xs.x; A1 += e1 * xs.x; A2 += e2 * xs.x; A3 += e3 * xs.x;
        B0 += e0 * xs.y; B1 += e1 * xs.y; B2 += e2 * xs.y; B3 += e3 * xs.y;
    }
    // epilogue: reconstruct 32-dim layer-1 output, ELU, layer-2 transform
    float dn[4] = {dn0 + 1e-16f, dn1 + 1e-16f, dn2 + 1e-16f, dn3 + 1e-16f};
    float Ah[4] = {A0, A1, A2, A3};
    float Bh[4] = {B0, B1, B2, B3};
    float h20 = 0.f, h21 = 0.f;
#pragma unroll
    for (int hd = 0; hd < 4; hd++) {
        float inv = 1.f / dn[hd];
#pragma unroll
        for (int c = 0; c < 8; c++) {
            int k = hd * 8 + c;
            float acc = Ah[hd] * __ldg(&W1[k]) + Bh[hd] * __ldg(&W1[32 + k]);
            float o = acc * inv + __ldg(&b1[k]);
            o = o > 0.f ? o : (expf(o) - 1.f);       // ELU
            h20 += o * __ldg(&W2[2 * k + 0]);
            h21 += o * __ldg(&W2[2 * k + 1]);
        }
    }
    float s2 = h20 * __ldg(&as2[0]) + h21 * __ldg(&as2[1]);
    float d2 = h20 * __ldg(&ad2[0]) + h21 * __ldg(&ad2[1]);
    g_nd2[n] = make_float4(s2, d2, h20, h21);
}

// ============================================================================
// KL2: per-node layer-2: loop incoming edges, fused final output.
// ============================================================================
__global__ void kL2(float* __restrict__ out, const float* __restrict__ b2) {
    int n = blockIdx.x * blockDim.x + threadIdx.x;
    if (n >= NN) return;
    float4 own = g_nd2[n];          // (als2, ald2, h2x, h2y)
    float ald2 = own.y;
    // self-loop seed
    float w = __expf(lrelu(own.x + ald2));
    float acc0 = w * own.z, acc1 = w * own.w, den = w;
    int beg = g_off[n];
    int end = beg + g_cnt[n];
#pragma unroll 4
    for (int j = beg; j < end; j++) {
        int s = __ldg(&g_ss[j]);
        float4 ns = __ldg(&g_nd2[s]);
        float e = __expf(lrelu(ns.x + ald2));
        acc0 += e * ns.z;
        acc1 += e * ns.w;
        den  += e;
    }
    float inv = 1.f / (den + 1e-16f);
    out[2 * n + 0] = acc0 * inv + __ldg(&b2[0]);
    out[2 * n + 1] = acc1 * inv + __ldg(&b2[1]);
}

// ============================================================================
extern "C" void kernel_launch(void* const* d_in, const int* in_sizes, int n_in,
                              void* d_out, int out_size) {
    const float* x   = (const float*)d_in[0];
    const int*   ei  = (const int*)d_in[1];   // int64 in reference -> int32 in harness
    // d_in[2] = edge_attr (unused by the reference GATConv)
    const float* W1  = (const float*)d_in[3];
    const float* as1 = (const float*)d_in[4];
    const float* ad1 = (const float*)d_in[5];
    const float* b1  = (const float*)d_in[6];
    const float* W2  = (const float*)d_in[7];
    const float* as2 = (const float*)d_in[8];
    const float* ad2 = (const float*)d_in[9];
    const float* b2  = (const float*)d_in[10];

    int E = in_sizes[1] / 2;   // edge_index is [2, E]
    int NB = (NN + 255) / 256;
    int EB = (E + 255) / 256;

    k1_node<<<NB, 256>>>(x, W1, as1, ad1);
    khist<<<EB, 256>>>(ei, E);
    kscanA<<<SCAN_G, SCAN_B>>>();
    kscanB<<<1, 128>>>();
    kscanC<<<NB, 256>>>();
    kscatter<<<EB, 256>>>(ei, E);
    kL1<<<NB, 256>>>(W1, b1, W2, as2, ad2);
    kL2<<<NB, 256>>>((float*)d_out, b2);
}